// round 4
// baseline (speedup 1.0000x reference)
#include <cuda_runtime.h>
#include <cfloat>

#define POOL_H 7
#define POOL_W 7
#define SCALE 0.0625f
#define CHANS 256
#define FH 224
#define FW 224
#define N_ROIS 512
#define PER_CHAN (N_ROIS * POOL_H * POOL_W)   // 25088 work items per channel
#define TPB 256
#define BLOCKS_PER_CHAN (PER_CHAN / TPB)      // 98 exactly

// Replicate XLA-GPU's fp32 division: div.full.f32 (approximate, <=2ulp,
// NOT correctly rounded). This is the op the reference actually executed.
__device__ __forceinline__ float div_full(float a, float b) {
    float r;
    asm("div.full.f32 %0, %1, %2;" : "=f"(r) : "f"(a), "f"(b));
    return r;
}

// round_half_up(v * 0.0625): both ops provably exact in fp32 for v in [0,3584)
__device__ __forceinline__ int round_half_up_scaled(float v) {
    return (int)floorf(__fadd_rn(__fmul_rn(v, SCALE), 0.5f));
}

// Channel-major scheduling: block b -> channel c = b / 98. All work for one
// channel touches only 4 * 224*224*4B = 802KB of feat -> L2-resident.
__global__ void roipool_kernel(const float* __restrict__ feat,
                               const float* __restrict__ rois,
                               float* __restrict__ out) {
    int c   = blockIdx.x / BLOCKS_PER_CHAN;
    int rem = (blockIdx.x % BLOCKS_PER_CHAN) * TPB + threadIdx.x;  // < 25088
    int n   = rem / (POOL_H * POOL_W);
    int k   = rem % (POOL_H * POOL_W);
    int ph  = k / POOL_W;
    int pw  = k % POOL_W;

    const float* roi = rois + n * 5;
    int b  = (int)roi[0];
    int xs = round_half_up_scaled(roi[1]);
    int ys = round_half_up_scaled(roi[2]);
    int xe = round_half_up_scaled(roi[3]);
    int ye = round_half_up_scaled(roi[4]);

    int roi_w = max(xe - xs + 1, 1);
    int roi_h = max(ye - ys + 1, 1);

    // Match the reference's exact arithmetic: div.full.f32, then IEEE mul +
    // floor/ceil (exact ops on both sides).
    float bin_h = div_full((float)roi_h, (float)POOL_H);
    float bin_w = div_full((float)roi_w, (float)POOL_W);

    int hstart = min(max((int)floorf(__fmul_rn((float)ph,       bin_h)) + ys, 0), FH);
    int hend   = min(max((int)ceilf (__fmul_rn((float)(ph + 1), bin_h)) + ys, 0), FH);
    int wstart = min(max((int)floorf(__fmul_rn((float)pw,       bin_w)) + xs, 0), FW);
    int wend   = min(max((int)ceilf (__fmul_rn((float)(pw + 1), bin_w)) + xs, 0), FW);

    bool any = (hstart < hend) && (wstart < wend);

    const float* fmap = feat + ((long long)b * CHANS + c) * (FH * FW);

    float m = -FLT_MAX;
    for (int h = hstart; h < hend; ++h) {
        const float* row = fmap + h * FW;
        for (int w = wstart; w < wend; ++w) {
            m = fmaxf(m, __ldg(row + w));
        }
    }

    // Output layout: [n, c, ph, pw]
    out[((n * CHANS + c) * POOL_H + ph) * POOL_W + pw] = any ? m : 0.0f;
}

extern "C" void kernel_launch(void* const* d_in, const int* in_sizes, int n_in,
                              void* d_out, int out_size) {
    const float* feat;
    const float* rois;
    if (in_sizes[0] > in_sizes[1]) {
        feat = (const float*)d_in[0];
        rois = (const float*)d_in[1];
    } else {
        feat = (const float*)d_in[1];
        rois = (const float*)d_in[0];
    }
    float* out = (float*)d_out;

    int blocks = CHANS * BLOCKS_PER_CHAN;  // 256 * 98 = 25088
    roipool_kernel<<<blocks, TPB>>>(feat, rois, out);
}